// round 16
// baseline (speedup 1.0000x reference)
#include <cuda_runtime.h>
#include <cuda_bf16.h>
#include <cuda_fp16.h>
#include <math.h>
#include <cstdint>

#define B_      4
#define SEQ_    1024
#define DIM_    1024
#define HEADS_  16
#define DH_     64
#define MEM_    1024
#define CMEM_   256
#define KV_     2304
#define TOTMEM_ 1280
#define SCALE_  0.125f
#define SCALE2_ 0.18033688011112042f   /* 0.125 * log2(e) */

typedef unsigned long long ull;

#define NEG_INF (__int_as_float(0xff800000))

__device__ __forceinline__ uint32_t smem_u32(const void* p) {
    uint32_t a;
    asm("{ .reg .u64 t; cvta.to.shared.u64 t, %1; cvt.u32.u64 %0, t; }" : "=r"(a) : "l"(p));
    return a;
}
__device__ __forceinline__ void ldm_x4(uint32_t* r, uint32_t addr) {
    asm volatile("ldmatrix.sync.aligned.m8n8.x4.shared.b16 {%0,%1,%2,%3}, [%4];"
        : "=r"(r[0]), "=r"(r[1]), "=r"(r[2]), "=r"(r[3]) : "r"(addr));
}
__device__ __forceinline__ void ldm_x4_t(uint32_t* r, uint32_t addr) {
    asm volatile("ldmatrix.sync.aligned.m8n8.x4.trans.shared.b16 {%0,%1,%2,%3}, [%4];"
        : "=r"(r[0]), "=r"(r[1]), "=r"(r[2]), "=r"(r[3]) : "r"(addr));
}
__device__ __forceinline__ void mma_hf(float* c, const uint32_t* a, const uint32_t* b) {
    asm volatile("mma.sync.aligned.m16n8k16.row.col.f32.f16.f16.f32 "
        "{%0,%1,%2,%3}, {%4,%5,%6,%7}, {%8,%9}, {%0,%1,%2,%3};"
        : "+f"(c[0]), "+f"(c[1]), "+f"(c[2]), "+f"(c[3])
        : "r"(a[0]), "r"(a[1]), "r"(a[2]), "r"(a[3]), "r"(b[0]), "r"(b[1]));
}
#define CP16(d, s)  asm volatile("cp.async.cg.shared.global [%0], [%1], 16;" :: "r"(d), "l"(s))
#define CPCOMMIT()  asm volatile("cp.async.commit_group;" ::: "memory")
#define CPWAIT(n)   asm volatile("cp.async.wait_group %0;" :: "n"(n) : "memory")

__device__ __forceinline__ float ex2f(float x) {
    float y; asm("ex2.approx.f32 %0, %1;" : "=f"(y) : "f"(x)); return y;
}
__device__ __forceinline__ uint32_t cvt_h2(float lo, float hi) {
    uint32_t c;
    asm("cvt.rn.f16x2.f32 %0, %1, %2;" : "=r"(c) : "f"(hi), "f"(lo));
    return c;
}
__device__ __forceinline__ uint32_t add_h2(uint32_t a, uint32_t b) {
    uint32_t r; asm("add.f16x2 %0, %1, %2;" : "=r"(r) : "r"(a), "r"(b)); return r;
}
__device__ __forceinline__ uint32_t max_h2(uint32_t a, uint32_t b) {
    uint32_t r; asm("max.f16x2 %0, %1, %2;" : "=r"(r) : "r"(a), "r"(b)); return r;
}
__device__ __forceinline__ uint32_t sub_ex2_h2(uint32_t t, uint32_t mn2) {
    uint32_t r;
    asm("sub.f16x2 %0, %1, %2;" : "=r"(r) : "r"(t), "r"(mn2));
    asm("ex2.approx.f16x2 %0, %1;" : "=r"(r) : "r"(r));
    return r;
}
__device__ __forceinline__ uint32_t dup_f16(float x) {
    uint32_t r;
    asm("cvt.rn.f16x2.f32 %0, %1, %2;" : "=r"(r) : "f"(x), "f"(x));
    return r;
}
__device__ __forceinline__ float h2_low_f32(uint32_t v) {
    __half2 h = *(__half2*)&v;
    return __half2float(__low2half(h));
}
__device__ __forceinline__ uint32_t pack_f16(float x, float y) {
    __half2 h = __floats2half2_rn(x, y);
    return *(uint32_t*)&h;
}
__device__ __forceinline__ void f16split(float v, __half& h, __half& l) {
    h = __float2half_rn(v);
    l = __float2half_rn(v - __half2float(h));
}

// ---------------------------------------------------------------------------
// Scratch
// ---------------------------------------------------------------------------
__device__ __half g_P   [(long long)B_*HEADS_*SEQ_*KV_];
__device__ float  g_pre [B_ * SEQ_ * DIM_];

__device__ __half g_kcf  [9216*1024];
__device__ __half g_qf   [4096*1024];
__device__ __half g_kf   [9216*1024];
__device__ __half g_vf   [9216*1024];
__device__ __half g_aof  [4096*1024];
__device__ __half g_WqTf [1024*1024];
__device__ __half g_WkvTf[2048*1024];
__device__ __half g_WoTf [1024*1024];
__device__ __half g_pef  [16*2304*64];
__device__ __half g_memfh[1024*4096],  g_memfl[1024*4096];
__device__ __half g_cwf  [1024*4096];

// ---------------------------------------------------------------------------
// Conversion kernels
// ---------------------------------------------------------------------------
__global__ void tof16_kernel(const float2* __restrict__ src, uint32_t* __restrict__ dst,
                             long long n2)
{
    long long i = (long long)blockIdx.x * blockDim.x + threadIdx.x;
    if (i < n2) {
        float2 v = src[i];
        dst[i] = pack_f16(v.x, v.y);
    }
}

__global__ void kvcat_f16(const float* __restrict__ cmem, const float* __restrict__ mem,
                          const float* __restrict__ x, uint2* __restrict__ dst)
{
    int r = blockIdx.x;
    int b = r / KV_, s = r - b * KV_;
    const float* src;
    if (s < CMEM_)        src = cmem + (long long)(b * CMEM_ + s) * DIM_;
    else if (s < TOTMEM_) src = mem  + (long long)(b * MEM_ + (s - CMEM_)) * DIM_;
    else                  src = x    + (long long)(b * SEQ_ + (s - TOTMEM_)) * DIM_;
    float4 v = *(const float4*)(src + threadIdx.x * 4);
    uint2 o;
    o.x = pack_f16(v.x, v.y);
    o.y = pack_f16(v.z, v.w);
    dst[(long long)r * 256 + threadIdx.x] = o;
}

__global__ void splitTf16_kernel(const float* __restrict__ src, __half* __restrict__ d,
                                 int K, int N)
{
    __shared__ float tile[32][33];
    int k0 = blockIdx.y * 32, n0 = blockIdx.x * 32;
#pragma unroll
    for (int i = 0; i < 4; i++) {
        int k = k0 + threadIdx.y + i * 8;
        tile[threadIdx.y + i * 8][threadIdx.x] = src[(long long)k * N + n0 + threadIdx.x];
    }
    __syncthreads();
#pragma unroll
    for (int i = 0; i < 4; i++) {
        int n = n0 + threadIdx.y + i * 8;
        d[(long long)n * K + k0 + threadIdx.x] =
            __float2half(tile[threadIdx.x][threadIdx.y + i * 8]);
    }
}

__global__ void splitf16_kernel(const float2* __restrict__ src, uint32_t* __restrict__ h,
                                uint32_t* __restrict__ l, long long n2)
{
    long long i = (long long)blockIdx.x * blockDim.x + threadIdx.x;
    if (i < n2) {
        float2 v = src[i];
        __half hx, lx, hy, ly;
        f16split(v.x, hx, lx);
        f16split(v.y, hy, ly);
        __half2 hh; hh.x = hx; hh.y = hy;
        __half2 ll; ll.x = lx; ll.y = ly;
        h[i] = *(uint32_t*)&hh;
        l[i] = *(uint32_t*)&ll;
    }
}

__global__ void convw_f16(const float* __restrict__ w, __half* __restrict__ d)
{
    long long idx = (long long)blockIdx.x * blockDim.x + threadIdx.x;
    if (idx >= (long long)1024 * 4096) return;
    int o = (int)(idx >> 12), k = (int)(idx & 4095);
    int r = k >> 10, i = k & 1023;
    d[idx] = __float2half(w[(long long)o * 4096 + i * 4 + r]);
}

// ---------------------------------------------------------------------------
// fp16 single-term tensor-core GEMM, cp.async double-buffered.
// AMAP 1: A rows are x embedded in kv-concat: r' = r + (r>>10)*1280 + 1280.
// EPI 4: fp16 out * SCALE2 -> C1.  EPI 5: kv split -> C1 (K), C2 (V).
// EPI 6: fp32 out + bias -> Cf.
// ---------------------------------------------------------------------------
template<int EPI, int AMAP>
__global__ __launch_bounds__(256, 2)
void hgemm(const __half* __restrict__ A, const __half* __restrict__ B,
           __half* __restrict__ C1, __half* __restrict__ C2,
           float* __restrict__ Cf, const float* __restrict__ bias,
           int M, int N, int K, int lda, int ldb, int ldc)
{
    extern __shared__ char sm[];
    const int m0 = blockIdx.y * 128, n0 = blockIdx.x * 128;
    const int tid = threadIdx.x, lane = tid & 31, w = tid >> 5;
    const int mw = (w >> 1) * 32, nw = (w & 1) * 64;
    const uint32_t sb = smem_u32(sm);

    const long long arow0 = AMAP ? ((long long)m0 + (m0 >> 10) * 1280 + 1280)
                                 : (long long)m0;

    float acc[2][8][4];
#pragma unroll
    for (int i = 0; i < 2; i++)
#pragma unroll
        for (int j = 0; j < 8; j++)
#pragma unroll
            for (int k = 0; k < 4; k++) acc[i][j][k] = 0.f;

    const uint32_t aoff = (mw + (lane & 15)) * 80 + (lane >> 4) * 16;
    const uint32_t boff = (nw + ((lane >> 4) << 3) + (lane & 7)) * 80 + ((lane >> 3) & 1) * 16;

    auto issue = [&](int k0, int buf) {
        uint32_t dstb = sb + buf * 20480;
#pragma unroll
        for (int u = 0; u < 4; u++) {
            int id = tid * 4 + u;
            int mat = id >> 9, rem = id & 511;
            int r = rem >> 2, c = rem & 3;
            uint32_t so = r * 80 + c * 16;
            if (mat == 0) CP16(dstb + so,         A + (arow0 + r) * lda + k0 + c * 8);
            else          CP16(dstb + 10240 + so, B + (long long)(n0 + r) * ldb + k0 + c * 8);
        }
    };

    const int nk = K >> 5;
    issue(0, 0); CPCOMMIT();
    for (int i = 0; i < nk; i++) {
        if (i + 1 < nk) { issue((i + 1) * 32, (i + 1) & 1); CPCOMMIT(); CPWAIT(1); }
        else CPWAIT(0);
        __syncthreads();
        const uint32_t st = sb + (i & 1) * 20480;
        const uint32_t sA = st, sB = st + 10240;
#pragma unroll
        for (int ks = 0; ks < 2; ks++) {
            uint32_t a0[4], a1[4];
            ldm_x4(a0, sA + aoff + ks * 32);
            ldm_x4(a1, sA + aoff + 1280 + ks * 32);
#pragma unroll
            for (int p = 0; p < 4; p++) {
                uint32_t b[4];
                ldm_x4(b, sB + boff + p * 1280 + ks * 32);
                mma_hf(acc[0][2*p],   a0, b);
                mma_hf(acc[0][2*p+1], a0, b + 2);
                mma_hf(acc[1][2*p],   a1, b);
                mma_hf(acc[1][2*p+1], a1, b + 2);
            }
        }
        __syncthreads();
    }

#pragma unroll
    for (int mf = 0; mf < 2; mf++)
#pragma unroll
    for (int nf = 0; nf < 8; nf++) {
        float* c = acc[mf][nf];
        int m = m0 + mw + mf * 16 + (lane >> 2);
        int n = n0 + nw + nf * 8 + (lane & 3) * 2;
        if (EPI == 4) {
            *(uint32_t*)&C1[(long long)m * ldc + n]       = pack_f16(c[0] * SCALE2_, c[1] * SCALE2_);
            *(uint32_t*)&C1[(long long)(m + 8) * ldc + n] = pack_f16(c[2] * SCALE2_, c[3] * SCALE2_);
        } else if (EPI == 5) {
            if (n < 1024) {
                *(uint32_t*)&C1[(long long)m * 1024 + n]       = pack_f16(c[0], c[1]);
                *(uint32_t*)&C1[(long long)(m + 8) * 1024 + n] = pack_f16(c[2], c[3]);
            } else {
                int nv = n - 1024;
                *(uint32_t*)&C2[(long long)m * 1024 + nv]       = pack_f16(c[0], c[1]);
                *(uint32_t*)&C2[(long long)(m + 8) * 1024 + nv] = pack_f16(c[2], c[3]);
            }
        } else {
            float b0 = bias[n], b1 = bias[n + 1];
            *(float2*)&Cf[(long long)m * ldc + n]       = make_float2(c[0] + b0, c[1] + b1);
            *(float2*)&Cf[(long long)(m + 8) * ldc + n] = make_float2(c[2] + b0, c[3] + b1);
        }
    }
}

// ---------------------------------------------------------------------------
// fp16 2-term GEMM (conv path).
// ---------------------------------------------------------------------------
__global__ __launch_bounds__(256, 2)
void hgemm2(const __half* __restrict__ Ah, const __half* __restrict__ Al,
            const __half* __restrict__ B, float* __restrict__ C,
            int M, int N, int K, int lda, int ldb, int ldc,
            const float* __restrict__ bias)
{
    extern __shared__ char sm[];
    const int m0 = blockIdx.y * 128, n0 = blockIdx.x * 128;
    const int tid = threadIdx.x, lane = tid & 31, w = tid >> 5;
    const int mw = (w >> 1) * 32, nw = (w & 1) * 64;
    const uint32_t sb = smem_u32(sm);

    float acc[2][8][4];
#pragma unroll
    for (int i = 0; i < 2; i++)
#pragma unroll
        for (int j = 0; j < 8; j++)
#pragma unroll
            for (int k = 0; k < 4; k++) acc[i][j][k] = 0.f;

    const uint32_t aoff = (mw + (lane & 15)) * 80 + (lane >> 4) * 16;
    const uint32_t boff = (nw + ((lane >> 4) << 3) + (lane & 7)) * 80 + ((lane >> 3) & 1) * 16;

    auto issue = [&](int k0, int buf) {
        uint32_t dstb = sb + buf * 30720;
#pragma unroll
        for (int u = 0; u < 6; u++) {
            int id = tid * 6 + u;
            int mat = id >> 9, rem = id & 511;
            int r = rem >> 2, c = rem & 3;
            uint32_t so = r * 80 + c * 16;
            const __half* src = (mat == 0) ? Ah + (long long)(m0 + r) * lda + k0 + c * 8
                              : (mat == 1) ? Al + (long long)(m0 + r) * lda + k0 + c * 8
                                           : B  + (long long)(n0 + r) * ldb + k0 + c * 8;
            CP16(dstb + mat * 10240 + so, src);
        }
    };

    const int nk = K >> 5;
    issue(0, 0); CPCOMMIT();
    for (int i = 0; i < nk; i++) {
        if (i + 1 < nk) { issue((i + 1) * 32, (i + 1) & 1); CPCOMMIT(); CPWAIT(1); }
        else CPWAIT(0);
        __syncthreads();
        const uint32_t st = sb + (i & 1) * 30720;
        const uint32_t sAh = st, sAl = st + 10240, sB = st + 20480;
#pragma unroll
        for (int ks = 0; ks < 2; ks++) {
            uint32_t a0h[4], a1h[4], a0l[4], a1l[4];
            ldm_x4(a0h, sAh + aoff + ks * 32);
            ldm_x4(a1h, sAh + aoff + 1280 + ks * 32);
            ldm_x4(a0l, sAl + aoff + ks * 32);
            ldm_x4(a1l, sAl + aoff + 1280 + ks * 32);
#pragma unroll
            for (int p = 0; p < 4; p++) {
                uint32_t b[4];
                ldm_x4(b, sB + boff + p * 1280 + ks * 32);
                mma_hf(acc[0][2*p],   a0h, b);
                mma_hf(acc[0][2*p],   a0l, b);
                mma_hf(acc[0][2*p+1], a0h, b + 2);
                mma_hf(acc[0][2*p+1], a0l, b + 2);
                mma_hf(acc[1][2*p],   a1h, b);
                mma_hf(acc[1][2*p],   a1l, b);
                mma_hf(acc[1][2*p+1], a1h, b + 2);
                mma_hf(acc[1][2*p+1], a1l, b + 2);
            }
        }
        __syncthreads();
    }

#pragma unroll
    for (int mf = 0; mf < 2; mf++)
#pragma unroll
    for (int nf = 0; nf < 8; nf++) {
        float* c = acc[mf][nf];
        int m = m0 + mw + mf * 16 + (lane >> 2);
        int n = n0 + nw + nf * 8 + (lane & 3) * 2;
        float b0 = bias[n], b1 = bias[n + 1];
        *(float2*)&C[(long long)m * ldc + n]       = make_float2(c[0] + b0, c[1] + b1);
        *(float2*)&C[(long long)(m + 8) * ldc + n] = make_float2(c[2] + b0, c[3] + b1);
    }
}

// ---------------------------------------------------------------------------
// P GEMM v2: 512 threads, 128x256 tile, fp16 single-term, K=64,
// rel-shift scatter -> fp16 P. Grid (9, 8, 64).
// smem: A 128x144B + B 256x144B = 55296 B (dynamic).
// ---------------------------------------------------------------------------
__global__ __launch_bounds__(512)
void p_gemm(const __half* __restrict__ qf, const __half* __restrict__ pef,
            __half* __restrict__ P)
{
    extern __shared__ char sm[];
    const int m0 = blockIdx.y * 128, n0 = blockIdx.x * 256;
    if (m0 + n0 + 382 < 1023) return;   // whole 128x256 tile shifts below col 0
    const int z = blockIdx.z, zb = z >> 4, zh = z & 15;

    const int tid = threadIdx.x, lane = tid & 31, w = tid >> 5;
    const int mw = (w >> 2) * 32, nw = (w & 3) * 64;
    const uint32_t sb = smem_u32(sm);
    const uint32_t sA = sb, sB = sb + 18432;

    const __half* abase = qf  + ((long long)zb * SEQ_ + m0) * 1024 + zh * 64;
    const __half* bbase = pef + (long long)zh * KV_ * 64 + (long long)n0 * 64;
#pragma unroll
    for (int u = 0; u < 6; u++) {
        int id = tid * 6 + u;              // 0..3071 = 384 rows x 8 chunks
        int r = id >> 3, c = id & 7;
        uint32_t so = (r < 128) ? (sA - sb) + r * 144 + c * 16
                                : (sB - sb) + (r - 128) * 144 + c * 16;
        const __half* src = (r < 128) ? abase + (long long)r * 1024 + c * 8
                                      : bbase + (long long)(r - 128) * 64 + c * 8;
        CP16(sb + so, src);
    }
    CPCOMMIT(); CPWAIT(0);
    __syncthreads();

    float acc[2][8][4];
#pragma unroll
    for (int i = 0; i < 2; i++)
#pragma unroll
        for (int j = 0; j < 8; j++)
#pragma unroll
            for (int k = 0; k < 4; k++) acc[i][j][k] = 0.f;

    const uint32_t aoff = (mw + (lane & 15)) * 144 + (lane >> 4) * 16;
    const uint32_t boff = (nw + ((lane >> 4) << 3) + (lane & 7)) * 144 + ((lane >> 3) & 1) * 16;

#pragma unroll
    for (int ks = 0; ks < 4; ks++) {
        uint32_t a0[4], a1[4];
        ldm_x4(a0, sA + aoff + ks * 32);
        ldm_x4(a1, sA + aoff + 16 * 144 + ks * 32);
#pragma unroll
        for (int p = 0; p < 4; p++) {
            uint32_t b[4];
            ldm_x4(b, sB + boff + p * (16 * 144) + ks * 32);
            mma_hf(acc[0][2*p],   a0, b);
            mma_hf(acc[0][2*p+1], a0, b + 2);
            mma_hf(acc[1][2*p],   a1, b);
            mma_hf(acc[1][2*p+1], a1, b + 2);
        }
    }

    P += (long long)z * SEQ_ * KV_;
#pragma unroll
    for (int mf = 0; mf < 2; mf++)
#pragma unroll
    for (int nf = 0; nf < 8; nf++) {
        float* c = acc[mf][nf];
        int m = m0 + mw + mf * 16 + (lane >> 2);
        int n = n0 + nw + nf * 8 + (lane & 3) * 2;
        int cs = n + m - 1023;
        if (cs >= 0 && cs < KV_)         P[(long long)m * KV_ + cs]     = __float2half(c[0]);
        if (cs + 1 >= 0 && cs + 1 < KV_) P[(long long)m * KV_ + cs + 1] = __float2half(c[1]);
        int c2 = cs + 8;
        if (c2 >= 0 && c2 < KV_)         P[(long long)(m + 8) * KV_ + c2]     = __float2half(c[2]);
        if (c2 + 1 >= 0 && c2 + 1 < KV_) P[(long long)(m + 8) * KV_ + c2 + 1] = __float2half(c[3]);
    }
}

// ---------------------------------------------------------------------------
// Flash attention v8 (unchanged from R15): triple-buffered KV, fp16 softmax.
// smem: Q 36864 + 3 x 36864 = 147456 B.
// ---------------------------------------------------------------------------
#define FSTR 144
__global__ __launch_bounds__(512)
void flash_tc(const __half* __restrict__ qf, const __half* __restrict__ kf,
              const __half* __restrict__ vf, const __half* __restrict__ Pg,
              __half* __restrict__ aof)
{
    extern __shared__ char sm[];
    const uint32_t sb  = smem_u32(sm);
    const uint32_t sQ  = sb;
    const uint32_t sKV = sb + 36864;

    const int qt = 3 - blockIdx.x;
    const int z  = blockIdx.y;
    const int zb = z >> 4, zh = z & 15;
    const int t  = threadIdx.x;
    const int lane = t & 31, w = t >> 5;
    const int mw = w * 16;

    const long long qrow0  = (long long)zb * SEQ_ + qt * 256;
    const long long kvrow0 = (long long)zb * KV_;
    const __half* prow0 = Pg + ((long long)z * SEQ_) * KV_;

    auto issueKV = [&](int tile, int buf) {
        uint32_t dst = sKV + buf * 36864;
        const long long rb = kvrow0 + tile * 128;
#pragma unroll
        for (int u = 0; u < 2; u++) {
            int id = t * 2 + u;
            int r = id >> 3, c = id & 7;
            uint32_t so = r * FSTR + c * 16;
            const long long off = (rb + r) * 1024 + zh * 64 + c * 8;
            CP16(dst + so,         kf + off);
            CP16(dst + 18432 + so, vf + off);
        }
    };

    {
#pragma unroll
        for (int u = 0; u < 4; u++) {
            int id = t * 4 + u;
            int r = id >> 3, c = id & 7;
            CP16(sQ + r * FSTR + c * 16, qf + (qrow0 + r) * 1024 + zh * 64 + c * 8);
        }
        issueKV(0, 0);
        CPCOMMIT();
    }

    float o[8][4];
#pragma unroll
    for (int i = 0; i < 8; i++)
#pragma unroll
        for (int j = 0; j < 4; j++) o[i][j] = 0.f;
    float osum[4] = {0.f, 0.f, 0.f, 0.f};
    float mrow[2] = {NEG_INF, NEG_INF};

    const uint32_t aoff  = (mw + (lane & 15)) * FSTR + (lane >> 4) * 16;
    const uint32_t boff  = (((lane >> 4) << 3) + (lane & 7)) * FSTR + ((lane >> 3) & 1) * 16;
    const uint32_t boffV = (lane & 15) * FSTR + (lane >> 4) * 16;
    const uint32_t onesb[2] = {0x3C003C00u, 0x3C003C00u};

    const int i0g = qt * 256 + mw + (lane >> 2);
    const int i1g = i0g + 8;

    int buf = 0, nbuf = 1;
    const int ntiles = 2 * qt + 12;
    for (int tl = 0; tl < ntiles; tl++) {
        const int c0 = tl * 128;
        if (tl + 1 < ntiles) { issueKV(tl + 1, nbuf); CPCOMMIT(); CPWAIT(1); }
        else CPWAIT(0);
        __syncthreads();
        const uint32_t st = sKV + buf * 36864;
        const uint32_t sK = st, sV = st + 18432;
        buf = nbuf; nbuf = (nbuf == 2) ? 0 : nbuf + 1;

        float s[16][4];
#pragma unroll
        for (int f = 0; f < 16; f++)
#pragma unroll
            for (int j = 0; j < 4; j++) s[f][j] = 0.f;
#pragma unroll
        for (int ks = 0; ks < 4; ks++) {
            uint32_t aq[4];
            ldm_x4(aq, sQ + aoff + ks * 32);
#pragma unroll
            for (int p = 0; p < 8; p++) {
                uint32_t bk[4];
                ldm_x4(bk, sK + boff + p * (16 * FSTR) + ks * 32);
                mma_hf(s[2*p],   aq, bk);
                mma_hf(s[2*p+1], aq, bk + 2);
            }
        }

        const int lim0 = i0g + TOTMEM_ - c0;
        if (lim0 < 127) {
            const int lim1 = lim0 + 8;
#pragma unroll
            for (int f = 0; f < 16; f++) {
                int col = f * 8 + (lane & 3) * 2;
                if (col > lim0)     s[f][0] = NEG_INF;
                if (col + 1 > lim0) s[f][1] = NEG_INF;
                if (col > lim1)     s[f][2] = NEG_INF;
                if (col + 1 > lim1) s[f][3] = NEG_INF;
            }
        }

        uint32_t t0[16], t1[16];
        const __half* pr0 = prow0 + (long long)i0g * KV_ + c0 + (lane & 3) * 2;
        const __half* pr1 = prow0 + (long long)i1g * KV_ + c0 + (lane & 3) * 2;
#pragma unroll
        for (int f = 0; f < 16; f++) {
            t0[f] = add_h2(cvt_h2(s[f][0], s[f][1]), *(const uint32_t*)(pr0 + f * 8));
            t1[f] = add_h2(cvt_h2(s[f][2], s[f][3]), *(const uint32_t*)(pr1 + f * 8));
        }
        uint32_t m0 = t0[0], m1 = t1[0];
#pragma unroll
        for (int f = 1; f < 16; f++) { m0 = max_h2(m0, t0[f]); m1 = max_h2(m1, t1[f]); }
        m0 = max_h2(m0, __byte_perm(m0, m0, 0x1032));
        m1 = max_h2(m1, __byte_perm(m1, m1, 0x1032));
        m0 = max_h2(m0, __shfl_xor_sync(0xffffffffu, m0, 1));
        m0 = max_h2(m0, __shfl_xor_sync(0xffffffffu, m0, 2));
        m1 = max_h2(m1, __shfl_xor_sync(0xffffffffu, m1, 1));
        m1 = max_h2(m1, __shfl_xor_sync(0xffffffffu, m1, 2));
        const float mx0 = h2_low_f32(m0), mx1 = h2_low_f32(m1);
        const float mn0 = fmaxf(mrow[0], mx0), mn1 = fmaxf(mrow[1], mx1);
        if (mn0 > mrow[0]) {
            const float f0 = ex2f(mrow[0] - mn0);
#pragma unroll
            for (int of = 0; of < 8; of++) { o[of][0] *= f0; o[of][1] *= f0; }
            osum[0] *= f0; osum[1] *= f0;
            mrow[0] = mn0;
        }
        if (mn1 > mrow[1]) {
            const float f1 = ex2f(mrow[1] - mn1);
#pragma unroll
            for (int of = 0; of < 8; of++) { o[of][2] *= f1; o[of][3] *= f1; }
            osum[2] *= f1; osum[3] *= f1;
            mrow[1] = mn1;
        }
        const uint32_t mn20 = dup_f16(mn0), mn21 = dup_f16(mn1);

#pragma unroll
        for (int kk = 0; kk < 8; kk++) {
            uint32_t a[4];
            a[0] = sub_ex2_h2(t0[2*kk],   mn20);
            a[1] = sub_ex2_h2(t1[2*kk],   mn21);
            a[2] = sub_ex2_h2(t0[2*kk+1], mn20);
            a[3] = sub_ex2_h2(t1[2*kk+1], mn21);
#pragma unroll
            for (int pv = 0; pv < 4; pv++) {
                uint32_t bv[4];
                ldm_x4_t(bv, sV + boffV + kk * (16 * FSTR) + pv * 32);
                mma_hf(o[2*pv],   a, bv);
                mma_hf(o[2*pv+1], a, bv + 2);
            }
            mma_hf(osum, a, onesb);
        }
    }

    const float inv0 = 1.f / osum[0], inv1 = 1.f / osum[2];
    const long long base0 = ((long long)zb * SEQ_ + i0g) * DIM_ + zh * DH_;
#pragma unroll
    for (int of = 0; of < 8; of++) {
        int d = of * 8 + (lane & 3) * 2;
        *(uint32_t*)&aof[base0 + d]            = pack_f16(o[of][0] * inv0, o[of][1] * inv0);
        *(uint32_t*)&aof[base0 + 8 * DIM_ + d] = pack_f16(o[of][2] * inv1, o[of][3] * inv1);
    }
}

// ---------------------------------------------------------------------------
// Residual + LayerNorm, fused with new_mem copy + aux_loss.
// ---------------------------------------------------------------------------
__global__ __launch_bounds__(256)
void ln_kernel(const float* __restrict__ x, const float* __restrict__ pre,
               const float* __restrict__ g, const float* __restrict__ bta,
               float* __restrict__ out, float* __restrict__ out_mem,
               float* __restrict__ aux)
{
    const int row = blockIdx.x;
    const float* xr = x   + (long long)row * DIM_;
    const float* pr = pre + (long long)row * DIM_;
    float* om = out_mem + (long long)row * DIM_;
    __shared__ float sbuf[8], sbuf2[8];
    float s[4], xv[4];
    float lsum = 0.f, lsq = 0.f;
#pragma unroll
    for (int l = 0; l < 4; l++) {
        int c = threadIdx.x + l * 256;
        float xx = xr[c];
        xv[l] = xx;
        float t = xx + pr[c];
        s[l] = t; lsum += t; lsq += t * t;
    }
#pragma unroll
    for (int l = 0; l < 4; l++) om[threadIdx.x + l * 256] = xv[l];
    if (row == 0 && threadIdx.x == 0) aux[0] = 0.f;
    for (int o = 16; o; o >>= 1) {
        lsum += __shfl_xor_sync(0xffffffffu, lsum, o);
        lsq  += __shfl_xor_sync(0xffffffffu, lsq,  o);
    }
    if ((threadIdx.x & 31) == 0) { sbuf[threadIdx.x >> 5] = lsum; sbuf2[threadIdx.x >> 5] = lsq; }
    __syncthreads();
    float tsum = 0.f, tsq = 0.f;
#pragma unroll
    for (int w = 0; w < 8; w++) { tsum += sbuf[w]; tsq += sbuf2[w]; }
    float mu  = tsum * (1.f / DIM_);
    float var = tsq * (1.f / DIM_) - mu * mu;
    float invs = rsqrtf(var + 1e-5f);
#pragma unroll
    for (int l = 0; l < 4; l++) {
        int c = threadIdx.x + l * 256;
        out[(long long)row * DIM_ + c] = (s[l] - mu) * invs * g[c] + bta[c];
    }
}

// ---------------------------------------------------------------------------
extern "C" void kernel_launch(void* const* d_in, const int* in_sizes, int n_in,
                              void* d_out, int out_size)
{
    (void)in_sizes; (void)n_in;
    const float* x      = (const float*)d_in[0];
    const float* mem    = (const float*)d_in[1];
    const float* cmem   = (const float*)d_in[2];
    const float* pos    = (const float*)d_in[3];
    const float* Wq     = (const float*)d_in[5];
    const float* Wkv    = (const float*)d_in[6];
    const float* Wout   = (const float*)d_in[7];
    const float* bout   = (const float*)d_in[8];
    const float* ln_g   = (const float*)d_in[9];
    const float* ln_b   = (const float*)d_in[10];
    const float* conv_w = (const float*)d_in[11];
    const float* conv_b = (const float*)d_in[12];
    float* out = (float*)d_out;

    float* pre;
    __half *P, *kcf, *qfp, *kfp, *vfp, *aofp, *WqTf, *WkvTf, *WoTf, *pep;
    __half *memfh, *memfl, *cwf;
    cudaGetSymbolAddress((void**)&P,    g_P);
    cudaGetSymbolAddress((void**)&pre,  g_pre);
    cudaGetSymbolAddress((void**)&kcf,  g_kcf);
    cudaGetSymbolAddress((void**)&qfp,  g_qf);
    cudaGetSymbolAddress((void**)&kfp,  g_kf);
    cudaGetSymbolAddress((void**)&vfp,  g_vf);
    cudaGetSymbolAddress((void**)&aofp, g_aof);
    cudaGetSymbolAddress((void**)&WqTf, g_WqTf);
    cudaGetSymbolAddress((void**)&WkvTf,g_WkvTf);
    cudaGetSymbolAddress((void**)&WoTf, g_WoTf);
    cudaGetSymbolAddress((void**)&pep,  g_pef);
    cudaGetSymbolAddress((void**)&memfh,g_memfh);
    cudaGetSymbolAddress((void**)&memfl,g_memfl);
    cudaGetSymbolAddress((void**)&cwf,  g_cwf);

    const int HSM  = 40960;
    const int H2SM = 61440;
    const int PSM  = 55296;
    const int FSM  = 147456;
    cudaFuncSetAttribute((const void*)hgemm<4,1>, cudaFuncAttributeMaxDynamicSharedMemorySize, HSM);
    cudaFuncSetAttribute((const void*)hgemm<5,0>, cudaFuncAttributeMaxDynamicSharedMemorySize, HSM);
    cudaFuncSetAttribute((const void*)hgemm<6,0>, cudaFuncAttributeMaxDynamicSharedMemorySize, HSM);
    cudaFuncSetAttribute((const void*)hgemm2,     cudaFuncAttributeMaxDynamicSharedMemorySize, H2SM);
    cudaFuncSetAttribute((const void*)p_gemm,     cudaFuncAttributeMaxDynamicSharedMemorySize, PSM);
    cudaFuncSetAttribute((const void*)flash_tc,   cudaFuncAttributeMaxDynamicSharedMemorySize, FSM);

    // ---- conversions for kv GEMM ----
    kvcat_f16<<<9216, 256>>>(cmem, mem, x, (uint2*)kcf);
    splitTf16_kernel<<<dim3(64, 32), dim3(32, 8)>>>(Wkv, WkvTf, 1024, 2048);

    // ---- kv = concat @ Wkv ----
    hgemm<5,0><<<dim3(16, 72, 1), 256, HSM>>>(
        kcf, WkvTf, kfp, vfp, nullptr, nullptr, 9216, 2048, 1024, 1024, 1024, 1024);

    // ---- remaining conversions ----
    splitTf16_kernel<<<dim3(32, 32), dim3(32, 8)>>>(Wq, WqTf, 1024, 1024);
    splitTf16_kernel<<<dim3(32, 32), dim3(32, 8)>>>(Wout, WoTf, 1024, 1024);
    tof16_kernel<<<4608, 256>>>((const float2*)pos, (uint32_t*)pep, 1179648);
    splitf16_kernel<<<8192, 256>>>((const float2*)mem, (uint32_t*)memfh,
                                   (uint32_t*)memfl, 2097152);
    convw_f16<<<16384, 256>>>(conv_w, cwf);

    // ---- q = (x @ Wq) * SCALE2 ----
    hgemm<4,1><<<dim3(8, 32, 1), 256, HSM>>>(
        kcf, WqTf, qfp, nullptr, nullptr, nullptr, 4096, 1024, 1024, 1024, 1024, 1024);

    // ---- Pshift = shift(q @ pe^T) (128x256 tiles) ----
    p_gemm<<<dim3(9, 8, 64), 512, PSM>>>(qfp, pep, P);

    // ---- flash attention -> aof ----
    flash_tc<<<dim3(4, 64), 512, FSM>>>(qfp, kfp, vfp, P, aofp);

    // ---- pre = ao @ Wout + bout ----
    hgemm<6,0><<<dim3(8, 32, 1), 256, HSM>>>(
        aofp, WoTf, nullptr, nullptr, pre, bout, 4096, 1024, 1024, 1024, 1024, 1024);

    // ---- logits = LN(x + pre); fused new_mem copy + aux ----
    ln_kernel<<<4096, 256>>>(x, pre, ln_g, ln_b, out, out + 4194304,
                             out + (out_size - 1));

    // ---- new_cmem = mem[1024x4096] @ conv_w^T + conv_b (fp16 2-term) ----
    hgemm2<<<dim3(8, 8, 1), 256, H2SM>>>(
        memfh, memfl, cwf, out + 8388608, 1024, 1024, 4096, 4096, 4096, 1024, conv_b);
}

// round 17
// speedup vs baseline: 1.0279x; 1.0279x over previous
#include <cuda_runtime.h>
#include <cuda_bf16.h>
#include <cuda_fp16.h>
#include <math.h>
#include <cstdint>

#define B_      4
#define SEQ_    1024
#define DIM_    1024
#define HEADS_  16
#define DH_     64
#define MEM_    1024
#define CMEM_   256
#define KV_     2304
#define TOTMEM_ 1280
#define SCALE_  0.125f
#define SCALE2_ 0.18033688011112042f   /* 0.125 * log2(e) */

typedef unsigned long long ull;

#define NEG_INF (__int_as_float(0xff800000))

__device__ __forceinline__ uint32_t smem_u32(const void* p) {
    uint32_t a;
    asm("{ .reg .u64 t; cvta.to.shared.u64 t, %1; cvt.u32.u64 %0, t; }" : "=r"(a) : "l"(p));
    return a;
}
__device__ __forceinline__ void ldm_x4(uint32_t* r, uint32_t addr) {
    asm volatile("ldmatrix.sync.aligned.m8n8.x4.shared.b16 {%0,%1,%2,%3}, [%4];"
        : "=r"(r[0]), "=r"(r[1]), "=r"(r[2]), "=r"(r[3]) : "r"(addr));
}
__device__ __forceinline__ void ldm_x4_t(uint32_t* r, uint32_t addr) {
    asm volatile("ldmatrix.sync.aligned.m8n8.x4.trans.shared.b16 {%0,%1,%2,%3}, [%4];"
        : "=r"(r[0]), "=r"(r[1]), "=r"(r[2]), "=r"(r[3]) : "r"(addr));
}
__device__ __forceinline__ void mma_hf(float* c, const uint32_t* a, const uint32_t* b) {
    asm volatile("mma.sync.aligned.m16n8k16.row.col.f32.f16.f16.f32 "
        "{%0,%1,%2,%3}, {%4,%5,%6,%7}, {%8,%9}, {%0,%1,%2,%3};"
        : "+f"(c[0]), "+f"(c[1]), "+f"(c[2]), "+f"(c[3])
        : "r"(a[0]), "r"(a[1]), "r"(a[2]), "r"(a[3]), "r"(b[0]), "r"(b[1]));
}
#define CP16(d, s)  asm volatile("cp.async.cg.shared.global [%0], [%1], 16;" :: "r"(d), "l"(s))
#define CPCOMMIT()  asm volatile("cp.async.commit_group;" ::: "memory")
#define CPWAIT(n)   asm volatile("cp.async.wait_group %0;" :: "n"(n) : "memory")

__device__ __forceinline__ float ex2f(float x) {
    float y; asm("ex2.approx.f32 %0, %1;" : "=f"(y) : "f"(x)); return y;
}
__device__ __forceinline__ uint32_t cvt_h2(float lo, float hi) {
    uint32_t c;
    asm("cvt.rn.f16x2.f32 %0, %1, %2;" : "=r"(c) : "f"(hi), "f"(lo));
    return c;
}
__device__ __forceinline__ uint32_t add_h2(uint32_t a, uint32_t b) {
    uint32_t r; asm("add.f16x2 %0, %1, %2;" : "=r"(r) : "r"(a), "r"(b)); return r;
}
__device__ __forceinline__ uint32_t max_h2(uint32_t a, uint32_t b) {
    uint32_t r; asm("max.f16x2 %0, %1, %2;" : "=r"(r) : "r"(a), "r"(b)); return r;
}
__device__ __forceinline__ uint32_t sub_ex2_h2(uint32_t t, uint32_t mn2) {
    uint32_t r;
    asm("sub.f16x2 %0, %1, %2;" : "=r"(r) : "r"(t), "r"(mn2));
    asm("ex2.approx.f16x2 %0, %1;" : "=r"(r) : "r"(r));
    return r;
}
__device__ __forceinline__ uint32_t dup_f16(float x) {
    uint32_t r;
    asm("cvt.rn.f16x2.f32 %0, %1, %2;" : "=r"(r) : "f"(x), "f"(x));
    return r;
}
__device__ __forceinline__ float h2_low_f32(uint32_t v) {
    __half2 h = *(__half2*)&v;
    return __half2float(__low2half(h));
}
__device__ __forceinline__ uint32_t pack_f16(float x, float y) {
    __half2 h = __floats2half2_rn(x, y);
    return *(uint32_t*)&h;
}
__device__ __forceinline__ void f16split(float v, __half& h, __half& l) {
    h = __float2half_rn(v);
    l = __float2half_rn(v - __half2float(h));
}

// ---------------------------------------------------------------------------
// Scratch
// ---------------------------------------------------------------------------
__device__ __half g_P   [(long long)B_*HEADS_*SEQ_*KV_];
__device__ float  g_pre [B_ * SEQ_ * DIM_];

__device__ __half g_kcf  [9216*1024];
__device__ __half g_qf   [4096*1024];
__device__ __half g_kf   [9216*1024];
__device__ __half g_vf   [9216*1024];
__device__ __half g_aof  [4096*1024];
__device__ __half g_WqTf [1024*1024];
__device__ __half g_WkvTf[2048*1024];
__device__ __half g_WoTf [1024*1024];
__device__ __half g_pef  [16*2304*64];
__device__ __half g_memfh[1024*4096],  g_memfl[1024*4096];
__device__ __half g_cwf  [1024*4096];

// ---------------------------------------------------------------------------
// Conversion kernels
// ---------------------------------------------------------------------------
__global__ void tof16_kernel(const float2* __restrict__ src, uint32_t* __restrict__ dst,
                             long long n2)
{
    long long i = (long long)blockIdx.x * blockDim.x + threadIdx.x;
    if (i < n2) {
        float2 v = src[i];
        dst[i] = pack_f16(v.x, v.y);
    }
}

__global__ void kvcat_f16(const float* __restrict__ cmem, const float* __restrict__ mem,
                          const float* __restrict__ x, uint2* __restrict__ dst)
{
    int r = blockIdx.x;
    int b = r / KV_, s = r - b * KV_;
    const float* src;
    if (s < CMEM_)        src = cmem + (long long)(b * CMEM_ + s) * DIM_;
    else if (s < TOTMEM_) src = mem  + (long long)(b * MEM_ + (s - CMEM_)) * DIM_;
    else                  src = x    + (long long)(b * SEQ_ + (s - TOTMEM_)) * DIM_;
    float4 v = *(const float4*)(src + threadIdx.x * 4);
    uint2 o;
    o.x = pack_f16(v.x, v.y);
    o.y = pack_f16(v.z, v.w);
    dst[(long long)r * 256 + threadIdx.x] = o;
}

__global__ void splitTf16_kernel(const float* __restrict__ src, __half* __restrict__ d,
                                 int K, int N)
{
    __shared__ float tile[32][33];
    int k0 = blockIdx.y * 32, n0 = blockIdx.x * 32;
#pragma unroll
    for (int i = 0; i < 4; i++) {
        int k = k0 + threadIdx.y + i * 8;
        tile[threadIdx.y + i * 8][threadIdx.x] = src[(long long)k * N + n0 + threadIdx.x];
    }
    __syncthreads();
#pragma unroll
    for (int i = 0; i < 4; i++) {
        int n = n0 + threadIdx.y + i * 8;
        d[(long long)n * K + k0 + threadIdx.x] =
            __float2half(tile[threadIdx.x][threadIdx.y + i * 8]);
    }
}

__global__ void splitf16_kernel(const float2* __restrict__ src, uint32_t* __restrict__ h,
                                uint32_t* __restrict__ l, long long n2)
{
    long long i = (long long)blockIdx.x * blockDim.x + threadIdx.x;
    if (i < n2) {
        float2 v = src[i];
        __half hx, lx, hy, ly;
        f16split(v.x, hx, lx);
        f16split(v.y, hy, ly);
        __half2 hh; hh.x = hx; hh.y = hy;
        __half2 ll; ll.x = lx; ll.y = ly;
        h[i] = *(uint32_t*)&hh;
        l[i] = *(uint32_t*)&ll;
    }
}

__global__ void convw_f16(const float* __restrict__ w, __half* __restrict__ d)
{
    long long idx = (long long)blockIdx.x * blockDim.x + threadIdx.x;
    if (idx >= (long long)1024 * 4096) return;
    int o = (int)(idx >> 12), k = (int)(idx & 4095);
    int r = k >> 10, i = k & 1023;
    d[idx] = __float2half(w[(long long)o * 4096 + i * 4 + r]);
}

// ---------------------------------------------------------------------------
// fp16 single-term tensor-core GEMM, cp.async double-buffered.
// AMAP 1: A rows are x embedded in kv-concat: r' = r + (r>>10)*1280 + 1280.
// EPI 4: fp16 out * SCALE2 -> C1.  EPI 5: kv split -> C1 (K), C2 (V).
// EPI 6: fp32 out + bias -> Cf.
// ---------------------------------------------------------------------------
template<int EPI, int AMAP>
__global__ __launch_bounds__(256, 2)
void hgemm(const __half* __restrict__ A, const __half* __restrict__ B,
           __half* __restrict__ C1, __half* __restrict__ C2,
           float* __restrict__ Cf, const float* __restrict__ bias,
           int M, int N, int K, int lda, int ldb, int ldc)
{
    extern __shared__ char sm[];
    const int m0 = blockIdx.y * 128, n0 = blockIdx.x * 128;
    const int tid = threadIdx.x, lane = tid & 31, w = tid >> 5;
    const int mw = (w >> 1) * 32, nw = (w & 1) * 64;
    const uint32_t sb = smem_u32(sm);

    const long long arow0 = AMAP ? ((long long)m0 + (m0 >> 10) * 1280 + 1280)
                                 : (long long)m0;

    float acc[2][8][4];
#pragma unroll
    for (int i = 0; i < 2; i++)
#pragma unroll
        for (int j = 0; j < 8; j++)
#pragma unroll
            for (int k = 0; k < 4; k++) acc[i][j][k] = 0.f;

    const uint32_t aoff = (mw + (lane & 15)) * 80 + (lane >> 4) * 16;
    const uint32_t boff = (nw + ((lane >> 4) << 3) + (lane & 7)) * 80 + ((lane >> 3) & 1) * 16;

    auto issue = [&](int k0, int buf) {
        uint32_t dstb = sb + buf * 20480;
#pragma unroll
        for (int u = 0; u < 4; u++) {
            int id = tid * 4 + u;
            int mat = id >> 9, rem = id & 511;
            int r = rem >> 2, c = rem & 3;
            uint32_t so = r * 80 + c * 16;
            if (mat == 0) CP16(dstb + so,         A + (arow0 + r) * lda + k0 + c * 8);
            else          CP16(dstb + 10240 + so, B + (long long)(n0 + r) * ldb + k0 + c * 8);
        }
    };

    const int nk = K >> 5;
    issue(0, 0); CPCOMMIT();
    for (int i = 0; i < nk; i++) {
        if (i + 1 < nk) { issue((i + 1) * 32, (i + 1) & 1); CPCOMMIT(); CPWAIT(1); }
        else CPWAIT(0);
        __syncthreads();
        const uint32_t st = sb + (i & 1) * 20480;
        const uint32_t sA = st, sB = st + 10240;
#pragma unroll
        for (int ks = 0; ks < 2; ks++) {
            uint32_t a0[4], a1[4];
            ldm_x4(a0, sA + aoff + ks * 32);
            ldm_x4(a1, sA + aoff + 1280 + ks * 32);
#pragma unroll
            for (int p = 0; p < 4; p++) {
                uint32_t b[4];
                ldm_x4(b, sB + boff + p * 1280 + ks * 32);
                mma_hf(acc[0][2*p],   a0, b);
                mma_hf(acc[0][2*p+1], a0, b + 2);
                mma_hf(acc[1][2*p],   a1, b);
                mma_hf(acc[1][2*p+1], a1, b + 2);
            }
        }
        __syncthreads();
    }

#pragma unroll
    for (int mf = 0; mf < 2; mf++)
#pragma unroll
    for (int nf = 0; nf < 8; nf++) {
        float* c = acc[mf][nf];
        int m = m0 + mw + mf * 16 + (lane >> 2);
        int n = n0 + nw + nf * 8 + (lane & 3) * 2;
        if (EPI == 4) {
            *(uint32_t*)&C1[(long long)m * ldc + n]       = pack_f16(c[0] * SCALE2_, c[1] * SCALE2_);
            *(uint32_t*)&C1[(long long)(m + 8) * ldc + n] = pack_f16(c[2] * SCALE2_, c[3] * SCALE2_);
        } else if (EPI == 5) {
            if (n < 1024) {
                *(uint32_t*)&C1[(long long)m * 1024 + n]       = pack_f16(c[0], c[1]);
                *(uint32_t*)&C1[(long long)(m + 8) * 1024 + n] = pack_f16(c[2], c[3]);
            } else {
                int nv = n - 1024;
                *(uint32_t*)&C2[(long long)m * 1024 + nv]       = pack_f16(c[0], c[1]);
                *(uint32_t*)&C2[(long long)(m + 8) * 1024 + nv] = pack_f16(c[2], c[3]);
            }
        } else {
            float b0 = bias[n], b1 = bias[n + 1];
            *(float2*)&Cf[(long long)m * ldc + n]       = make_float2(c[0] + b0, c[1] + b1);
            *(float2*)&Cf[(long long)(m + 8) * ldc + n] = make_float2(c[2] + b0, c[3] + b1);
        }
    }
}

// ---------------------------------------------------------------------------
// fp16 2-term GEMM (conv path).
// ---------------------------------------------------------------------------
__global__ __launch_bounds__(256, 2)
void hgemm2(const __half* __restrict__ Ah, const __half* __restrict__ Al,
            const __half* __restrict__ B, float* __restrict__ C,
            int M, int N, int K, int lda, int ldb, int ldc,
            const float* __restrict__ bias)
{
    extern __shared__ char sm[];
    const int m0 = blockIdx.y * 128, n0 = blockIdx.x * 128;
    const int tid = threadIdx.x, lane = tid & 31, w = tid >> 5;
    const int mw = (w >> 1) * 32, nw = (w & 1) * 64;
    const uint32_t sb = smem_u32(sm);

    float acc[2][8][4];
#pragma unroll
    for (int i = 0; i < 2; i++)
#pragma unroll
        for (int j = 0; j < 8; j++)
#pragma unroll
            for (int k = 0; k < 4; k++) acc[i][j][k] = 0.f;

    const uint32_t aoff = (mw + (lane & 15)) * 80 + (lane >> 4) * 16;
    const uint32_t boff = (nw + ((lane >> 4) << 3) + (lane & 7)) * 80 + ((lane >> 3) & 1) * 16;

    auto issue = [&](int k0, int buf) {
        uint32_t dstb = sb + buf * 30720;
#pragma unroll
        for (int u = 0; u < 6; u++) {
            int id = tid * 6 + u;
            int mat = id >> 9, rem = id & 511;
            int r = rem >> 2, c = rem & 3;
            uint32_t so = r * 80 + c * 16;
            const __half* src = (mat == 0) ? Ah + (long long)(m0 + r) * lda + k0 + c * 8
                              : (mat == 1) ? Al + (long long)(m0 + r) * lda + k0 + c * 8
                                           : B  + (long long)(n0 + r) * ldb + k0 + c * 8;
            CP16(dstb + mat * 10240 + so, src);
        }
    };

    const int nk = K >> 5;
    issue(0, 0); CPCOMMIT();
    for (int i = 0; i < nk; i++) {
        if (i + 1 < nk) { issue((i + 1) * 32, (i + 1) & 1); CPCOMMIT(); CPWAIT(1); }
        else CPWAIT(0);
        __syncthreads();
        const uint32_t st = sb + (i & 1) * 30720;
        const uint32_t sAh = st, sAl = st + 10240, sB = st + 20480;
#pragma unroll
        for (int ks = 0; ks < 2; ks++) {
            uint32_t a0h[4], a1h[4], a0l[4], a1l[4];
            ldm_x4(a0h, sAh + aoff + ks * 32);
            ldm_x4(a1h, sAh + aoff + 1280 + ks * 32);
            ldm_x4(a0l, sAl + aoff + ks * 32);
            ldm_x4(a1l, sAl + aoff + 1280 + ks * 32);
#pragma unroll
            for (int p = 0; p < 4; p++) {
                uint32_t b[4];
                ldm_x4(b, sB + boff + p * 1280 + ks * 32);
                mma_hf(acc[0][2*p],   a0h, b);
                mma_hf(acc[0][2*p],   a0l, b);
                mma_hf(acc[0][2*p+1], a0h, b + 2);
                mma_hf(acc[0][2*p+1], a0l, b + 2);
                mma_hf(acc[1][2*p],   a1h, b);
                mma_hf(acc[1][2*p],   a1l, b);
                mma_hf(acc[1][2*p+1], a1h, b + 2);
                mma_hf(acc[1][2*p+1], a1l, b + 2);
            }
        }
        __syncthreads();
    }

#pragma unroll
    for (int mf = 0; mf < 2; mf++)
#pragma unroll
    for (int nf = 0; nf < 8; nf++) {
        float* c = acc[mf][nf];
        int m = m0 + mw + mf * 16 + (lane >> 2);
        int n = n0 + nw + nf * 8 + (lane & 3) * 2;
        float b0 = bias[n], b1 = bias[n + 1];
        *(float2*)&C[(long long)m * ldc + n]       = make_float2(c[0] + b0, c[1] + b1);
        *(float2*)&C[(long long)(m + 8) * ldc + n] = make_float2(c[2] + b0, c[3] + b1);
    }
}

// ---------------------------------------------------------------------------
// P GEMM (R15 version): 256 threads, 128x128 tile, fp16 single-term, K=64,
// rel-shift scatter -> fp16 P. Grid (18, 8, 64). 2 CTAs/SM.
// ---------------------------------------------------------------------------
__global__ __launch_bounds__(256)
void p_gemm(const __half* __restrict__ qf, const __half* __restrict__ pef,
            __half* __restrict__ P)
{
    __shared__ char sm[36864];
    const int m0 = blockIdx.y * 128, n0 = blockIdx.x * 128;
    if (m0 + n0 + 254 < 1023) return;
    const int z = blockIdx.z, zb = z >> 4, zh = z & 15;

    const int tid = threadIdx.x, lane = tid & 31, w = tid >> 5;
    const int mw = (w >> 1) * 32, nw = (w & 1) * 64;
    const uint32_t sb = smem_u32(sm);
    const uint32_t sA = sb, sB = sb + 18432;

    const __half* abase = qf  + ((long long)zb * SEQ_ + m0) * 1024 + zh * 64;
    const __half* bbase = pef + (long long)zh * KV_ * 64 + (long long)n0 * 64;
#pragma unroll
    for (int u = 0; u < 8; u++) {
        int id = tid * 8 + u;
        int mat = id >> 10, rem = id & 1023;
        int r = rem >> 3, c = rem & 7;
        uint32_t so = r * 144 + c * 16;
        if (mat == 0) CP16(sA + so, abase + (long long)r * 1024 + c * 8);
        else          CP16(sB + so, bbase + (long long)r * 64 + c * 8);
    }
    CPCOMMIT(); CPWAIT(0);
    __syncthreads();

    float acc[2][8][4];
#pragma unroll
    for (int i = 0; i < 2; i++)
#pragma unroll
        for (int j = 0; j < 8; j++)
#pragma unroll
            for (int k = 0; k < 4; k++) acc[i][j][k] = 0.f;

    const uint32_t aoff = (mw + (lane & 15)) * 144 + (lane >> 4) * 16;
    const uint32_t boff = (nw + ((lane >> 4) << 3) + (lane & 7)) * 144 + ((lane >> 3) & 1) * 16;

#pragma unroll
    for (int ks = 0; ks < 4; ks++) {
        uint32_t a0[4], a1[4];
        ldm_x4(a0, sA + aoff + ks * 32);
        ldm_x4(a1, sA + aoff + 16 * 144 + ks * 32);
#pragma unroll
        for (int p = 0; p < 4; p++) {
            uint32_t b[4];
            ldm_x4(b, sB + boff + p * (16 * 144) + ks * 32);
            mma_hf(acc[0][2*p],   a0, b);
            mma_hf(acc[0][2*p+1], a0, b + 2);
            mma_hf(acc[1][2*p],   a1, b);
            mma_hf(acc[1][2*p+1], a1, b + 2);
        }
    }

    P += (long long)z * SEQ_ * KV_;
#pragma unroll
    for (int mf = 0; mf < 2; mf++)
#pragma unroll
    for (int nf = 0; nf < 8; nf++) {
        float* c = acc[mf][nf];
        int m = m0 + mw + mf * 16 + (lane >> 2);
        int n = n0 + nw + nf * 8 + (lane & 3) * 2;
        int cs = n + m - 1023;
        if (cs >= 0 && cs < KV_)         P[(long long)m * KV_ + cs]     = __float2half(c[0]);
        if (cs + 1 >= 0 && cs + 1 < KV_) P[(long long)m * KV_ + cs + 1] = __float2half(c[1]);
        int c2 = cs + 8;
        if (c2 >= 0 && c2 < KV_)         P[(long long)(m + 8) * KV_ + c2]     = __float2half(c[2]);
        if (c2 + 1 >= 0 && c2 + 1 < KV_) P[(long long)(m + 8) * KV_ + c2 + 1] = __float2half(c[3]);
    }
}

// ---------------------------------------------------------------------------
// Flash attention v8: triple-buffered KV, fp16 softmax, 256 Q-rows, 512 thr.
// smem: Q 36864 + 3 x 36864 = 147456 B.
// ---------------------------------------------------------------------------
#define FSTR 144
__global__ __launch_bounds__(512)
void flash_tc(const __half* __restrict__ qf, const __half* __restrict__ kf,
              const __half* __restrict__ vf, const __half* __restrict__ Pg,
              __half* __restrict__ aof)
{
    extern __shared__ char sm[];
    const uint32_t sb  = smem_u32(sm);
    const uint32_t sQ  = sb;
    const uint32_t sKV = sb + 36864;

    const int qt = 3 - blockIdx.x;
    const int z  = blockIdx.y;
    const int zb = z >> 4, zh = z & 15;
    const int t  = threadIdx.x;
    const int lane = t & 31, w = t >> 5;
    const int mw = w * 16;

    const long long qrow0  = (long long)zb * SEQ_ + qt * 256;
    const long long kvrow0 = (long long)zb * KV_;
    const __half* prow0 = Pg + ((long long)z * SEQ_) * KV_;

    auto issueKV = [&](int tile, int buf) {
        uint32_t dst = sKV + buf * 36864;
        const long long rb = kvrow0 + tile * 128;
#pragma unroll
        for (int u = 0; u < 2; u++) {
            int id = t * 2 + u;
            int r = id >> 3, c = id & 7;
            uint32_t so = r * FSTR + c * 16;
            const long long off = (rb + r) * 1024 + zh * 64 + c * 8;
            CP16(dst + so,         kf + off);
            CP16(dst + 18432 + so, vf + off);
        }
    };

    {
#pragma unroll
        for (int u = 0; u < 4; u++) {
            int id = t * 4 + u;
            int r = id >> 3, c = id & 7;
            CP16(sQ + r * FSTR + c * 16, qf + (qrow0 + r) * 1024 + zh * 64 + c * 8);
        }
        issueKV(0, 0);
        CPCOMMIT();
    }

    float o[8][4];
#pragma unroll
    for (int i = 0; i < 8; i++)
#pragma unroll
        for (int j = 0; j < 4; j++) o[i][j] = 0.f;
    float osum[4] = {0.f, 0.f, 0.f, 0.f};
    float mrow[2] = {NEG_INF, NEG_INF};

    const uint32_t aoff  = (mw + (lane & 15)) * FSTR + (lane >> 4) * 16;
    const uint32_t boff  = (((lane >> 4) << 3) + (lane & 7)) * FSTR + ((lane >> 3) & 1) * 16;
    const uint32_t boffV = (lane & 15) * FSTR + (lane >> 4) * 16;
    const uint32_t onesb[2] = {0x3C003C00u, 0x3C003C00u};

    const int i0g = qt * 256 + mw + (lane >> 2);
    const int i1g = i0g + 8;

    int buf = 0, nbuf = 1;
    const int ntiles = 2 * qt + 12;
    for (int tl = 0; tl < ntiles; tl++) {
        const int c0 = tl * 128;
        if (tl + 1 < ntiles) { issueKV(tl + 1, nbuf); CPCOMMIT(); CPWAIT(1); }
        else CPWAIT(0);
        __syncthreads();
        const uint32_t st = sKV + buf * 36864;
        const uint32_t sK = st, sV = st + 18432;
        buf = nbuf; nbuf = (nbuf == 2) ? 0 : nbuf + 1;

        float s[16][4];
#pragma unroll
        for (int f = 0; f < 16; f++)
#pragma unroll
            for (int j = 0; j < 4; j++) s[f][j] = 0.f;
#pragma unroll
        for (int ks = 0; ks < 4; ks++) {
            uint32_t aq[4];
            ldm_x4(aq, sQ + aoff + ks * 32);
#pragma unroll
            for (int p = 0; p < 8; p++) {
                uint32_t bk[4];
                ldm_x4(bk, sK + boff + p * (16 * FSTR) + ks * 32);
                mma_hf(s[2*p],   aq, bk);
                mma_hf(s[2*p+1], aq, bk + 2);
            }
        }

        const int lim0 = i0g + TOTMEM_ - c0;
        if (lim0 < 127) {
            const int lim1 = lim0 + 8;
#pragma unroll
            for (int f = 0; f < 16; f++) {
                int col = f * 8 + (lane & 3) * 2;
                if (col > lim0)     s[f][0] = NEG_INF;
                if (col + 1 > lim0) s[f][1] = NEG_INF;
                if (col > lim1)     s[f][2] = NEG_INF;
                if (col + 1 > lim1) s[f][3] = NEG_INF;
            }
        }

        uint32_t t0[16], t1[16];
        const __half* pr0 = prow0 + (long long)i0g * KV_ + c0 + (lane & 3) * 2;
        const __half* pr1 = prow0 + (long long)i1g * KV_ + c0 + (lane & 3) * 2;
#pragma unroll
        for (int f = 0; f < 16; f++) {
            t0[f] = add_h2(cvt_h2(s[f][0], s[f][1]), *(const uint32_t*)(pr0 + f * 8));
            t1[f] = add_h2(cvt_h2(s[f][2], s[f][3]), *(const uint32_t*)(pr1 + f * 8));
        }
        uint32_t m0 = t0[0], m1 = t1[0];
#pragma unroll
        for (int f = 1; f < 16; f++) { m0 = max_h2(m0, t0[f]); m1 = max_h2(m1, t1[f]); }
        m0 = max_h2(m0, __byte_perm(m0, m0, 0x1032));
        m1 = max_h2(m1, __byte_perm(m1, m1, 0x1032));
        m0 = max_h2(m0, __shfl_xor_sync(0xffffffffu, m0, 1));
        m0 = max_h2(m0, __shfl_xor_sync(0xffffffffu, m0, 2));
        m1 = max_h2(m1, __shfl_xor_sync(0xffffffffu, m1, 1));
        m1 = max_h2(m1, __shfl_xor_sync(0xffffffffu, m1, 2));
        const float mx0 = h2_low_f32(m0), mx1 = h2_low_f32(m1);
        const float mn0 = fmaxf(mrow[0], mx0), mn1 = fmaxf(mrow[1], mx1);
        if (mn0 > mrow[0]) {
            const float f0 = ex2f(mrow[0] - mn0);
#pragma unroll
            for (int of = 0; of < 8; of++) { o[of][0] *= f0; o[of][1] *= f0; }
            osum[0] *= f0; osum[1] *= f0;
            mrow[0] = mn0;
        }
        if (mn1 > mrow[1]) {
            const float f1 = ex2f(mrow[1] - mn1);
#pragma unroll
            for (int of = 0; of < 8; of++) { o[of][2] *= f1; o[of][3] *= f1; }
            osum[2] *= f1; osum[3] *= f1;
            mrow[1] = mn1;
        }
        const uint32_t mn20 = dup_f16(mn0), mn21 = dup_f16(mn1);

#pragma unroll
        for (int kk = 0; kk < 8; kk++) {
            uint32_t a[4];
            a[0] = sub_ex2_h2(t0[2*kk],   mn20);
            a[1] = sub_ex2_h2(t1[2*kk],   mn21);
            a[2] = sub_ex2_h2(t0[2*kk+1], mn20);
            a[3] = sub_ex2_h2(t1[2*kk+1], mn21);
#pragma unroll
            for (int pv = 0; pv < 4; pv++) {
                uint32_t bv[4];
                ldm_x4_t(bv, sV + boffV + kk * (16 * FSTR) + pv * 32);
                mma_hf(o[2*pv],   a, bv);
                mma_hf(o[2*pv+1], a, bv + 2);
            }
            mma_hf(osum, a, onesb);
        }
    }

    const float inv0 = 1.f / osum[0], inv1 = 1.f / osum[2];
    const long long base0 = ((long long)zb * SEQ_ + i0g) * DIM_ + zh * DH_;
#pragma unroll
    for (int of = 0; of < 8; of++) {
        int d = of * 8 + (lane & 3) * 2;
        *(uint32_t*)&aof[base0 + d]            = pack_f16(o[of][0] * inv0, o[of][1] * inv0);
        *(uint32_t*)&aof[base0 + 8 * DIM_ + d] = pack_f16(o[of][2] * inv1, o[of][3] * inv1);
    }
}

// ---------------------------------------------------------------------------
// Residual + LayerNorm, fused with new_mem copy + aux_loss.
// ---------------------------------------------------------------------------
__global__ __launch_bounds__(256)
void ln_kernel(const float* __restrict__ x, const float* __restrict__ pre,
               const float* __restrict__ g, const float* __restrict__ bta,
               float* __restrict__ out, float* __restrict__ out_mem,
               float* __restrict__ aux)
{
    const int row = blockIdx.x;
    const float* xr = x   + (long long)row * DIM_;
    const float* pr = pre + (long long)row * DIM_;
    float* om = out_mem + (long long)row * DIM_;
    __shared__ float sbuf[8], sbuf2[8];
    float s[4], xv[4];
    float lsum = 0.f, lsq = 0.f;
#pragma unroll
    for (int l = 0; l < 4; l++) {
        int c = threadIdx.x + l * 256;
        float xx = xr[c];
        xv[l] = xx;
        float t = xx + pr[c];
        s[l] = t; lsum += t; lsq += t * t;
    }
#pragma unroll
    for (int l = 0; l < 4; l++) om[threadIdx.x + l * 256] = xv[l];
    if (row == 0 && threadIdx.x == 0) aux[0] = 0.f;
    for (int o = 16; o; o >>= 1) {
        lsum += __shfl_xor_sync(0xffffffffu, lsum, o);
        lsq  += __shfl_xor_sync(0xffffffffu, lsq,  o);
    }
    if ((threadIdx.x & 31) == 0) { sbuf[threadIdx.x >> 5] = lsum; sbuf2[threadIdx.x >> 5] = lsq; }
    __syncthreads();
    float tsum = 0.f, tsq = 0.f;
#pragma unroll
    for (int w = 0; w < 8; w++) { tsum += sbuf[w]; tsq += sbuf2[w]; }
    float mu  = tsum * (1.f / DIM_);
    float var = tsq * (1.f / DIM_) - mu * mu;
    float invs = rsqrtf(var + 1e-5f);
#pragma unroll
    for (int l = 0; l < 4; l++) {
        int c = threadIdx.x + l * 256;
        out[(long long)row * DIM_ + c] = (s[l] - mu) * invs * g[c] + bta[c];
    }
}

// ---------------------------------------------------------------------------
extern "C" void kernel_launch(void* const* d_in, const int* in_sizes, int n_in,
                              void* d_out, int out_size)
{
    (void)in_sizes; (void)n_in;
    const float* x      = (const float*)d_in[0];
    const float* mem    = (const float*)d_in[1];
    const float* cmem   = (const float*)d_in[2];
    const float* pos    = (const float*)d_in[3];
    const float* Wq     = (const float*)d_in[5];
    const float* Wkv    = (const float*)d_in[6];
    const float* Wout   = (const float*)d_in[7];
    const float* bout   = (const float*)d_in[8];
    const float* ln_g   = (const float*)d_in[9];
    const float* ln_b   = (const float*)d_in[10];
    const float* conv_w = (const float*)d_in[11];
    const float* conv_b = (const float*)d_in[12];
    float* out = (float*)d_out;

    float* pre;
    __half *P, *kcf, *qfp, *kfp, *vfp, *aofp, *WqTf, *WkvTf, *WoTf, *pep;
    __half *memfh, *memfl, *cwf;
    cudaGetSymbolAddress((void**)&P,    g_P);
    cudaGetSymbolAddress((void**)&pre,  g_pre);
    cudaGetSymbolAddress((void**)&kcf,  g_kcf);
    cudaGetSymbolAddress((void**)&qfp,  g_qf);
    cudaGetSymbolAddress((void**)&kfp,  g_kf);
    cudaGetSymbolAddress((void**)&vfp,  g_vf);
    cudaGetSymbolAddress((void**)&aofp, g_aof);
    cudaGetSymbolAddress((void**)&WqTf, g_WqTf);
    cudaGetSymbolAddress((void**)&WkvTf,g_WkvTf);
    cudaGetSymbolAddress((void**)&WoTf, g_WoTf);
    cudaGetSymbolAddress((void**)&pep,  g_pef);
    cudaGetSymbolAddress((void**)&memfh,g_memfh);
    cudaGetSymbolAddress((void**)&memfl,g_memfl);
    cudaGetSymbolAddress((void**)&cwf,  g_cwf);

    const int HSM  = 40960;
    const int H2SM = 61440;
    const int FSM  = 147456;
    cudaFuncSetAttribute((const void*)hgemm<4,1>, cudaFuncAttributeMaxDynamicSharedMemorySize, HSM);
    cudaFuncSetAttribute((const void*)hgemm<5,0>, cudaFuncAttributeMaxDynamicSharedMemorySize, HSM);
    cudaFuncSetAttribute((const void*)hgemm<6,0>, cudaFuncAttributeMaxDynamicSharedMemorySize, HSM);
    cudaFuncSetAttribute((const void*)hgemm2,     cudaFuncAttributeMaxDynamicSharedMemorySize, H2SM);
    cudaFuncSetAttribute((const void*)flash_tc,   cudaFuncAttributeMaxDynamicSharedMemorySize, FSM);

    // ---- conversions for kv GEMM ----
    kvcat_f16<<<9216, 256>>>(cmem, mem, x, (uint2*)kcf);
    splitTf16_kernel<<<dim3(64, 32), dim3(32, 8)>>>(Wkv, WkvTf, 1024, 2048);

    // ---- kv = concat @ Wkv ----
    hgemm<5,0><<<dim3(16, 72, 1), 256, HSM>>>(
        kcf, WkvTf, kfp, vfp, nullptr, nullptr, 9216, 2048, 1024, 1024, 1024, 1024);

    // ---- remaining conversions ----
    splitTf16_kernel<<<dim3(32, 32), dim3(32, 8)>>>(Wq, WqTf, 1024, 1024);
    splitTf16_kernel<<<dim3(32, 32), dim3(32, 8)>>>(Wout, WoTf, 1024, 1024);
    tof16_kernel<<<4608, 256>>>((const float2*)pos, (uint32_t*)pep, 1179648);
    splitf16_kernel<<<8192, 256>>>((const float2*)mem, (uint32_t*)memfh,
                                   (uint32_t*)memfl, 2097152);
    convw_f16<<<16384, 256>>>(conv_w, cwf);

    // ---- q = (x @ Wq) * SCALE2 ----
    hgemm<4,1><<<dim3(8, 32, 1), 256, HSM>>>(
        kcf, WqTf, qfp, nullptr, nullptr, nullptr, 4096, 1024, 1024, 1024, 1024, 1024);

    // ---- Pshift = shift(q @ pe^T) (128x128 tiles, 2 CTAs/SM) ----
    p_gemm<<<dim3(18, 8, 64), 256>>>(qfp, pep, P);

    // ---- flash attention -> aof ----
    flash_tc<<<dim3(4, 64), 512, FSM>>>(qfp, kfp, vfp, P, aofp);

    // ---- pre = ao @ Wout + bout ----
    hgemm<6,0><<<dim3(8, 32, 1), 256, HSM>>>(
        aofp, WoTf, nullptr, nullptr, pre, bout, 4096, 1024, 1024, 1024, 1024, 1024);

    // ---- logits = LN(x + pre); fused new_mem copy + aux ----
    ln_kernel<<<4096, 256>>>(x, pre, ln_g, ln_b, out, out + 4194304,
                             out + (out_size - 1));

    // ---- new_cmem = mem[1024x4096] @ conv_w^T + conv_b (fp16 2-term) ----
    hgemm2<<<dim3(8, 8, 1), 256, H2SM>>>(
        memfh, memfl, cwf, out + 8388608, 1024, 1024, 4096, 4096, 4096, 1024, conv_b);
}